// round 2
// baseline (speedup 1.0000x reference)
#include <cuda_runtime.h>
#include <cuda_bf16.h>

// out[B,N] = x[B,K] @ W[K,N];  B=65536, K=512, N=64, all fp32.
// fp32 SIMT tiled GEMM baseline: block tile 128x64, BK=16, per-thread 8x4.

#define BATCH 65536
#define KDIM  512
#define NDIM  64
#define BM    128
#define BK    16
#define TM    8
#define TN    4
#define THREADS 256   // (BM/TM) * (NDIM/TN) = 16*16

__global__ __launch_bounds__(THREADS)
void NN_57844619543085_kernel(const float* __restrict__ x,
                              const float* __restrict__ W,
                              float* __restrict__ out) {
    __shared__ float xs[BK][BM];     // [k][row] -> broadcast-friendly reads
    __shared__ float ws[BK][NDIM];   // [k][col]

    const int t = threadIdx.x;
    const int block_row = blockIdx.x * BM;
    const int tr = t >> 4;   // 0..15 : row group (8 rows each)
    const int tc = t & 15;   // 0..15 : col group (4 cols each)

    float acc[TM][TN];
#pragma unroll
    for (int m = 0; m < TM; ++m)
#pragma unroll
        for (int n = 0; n < TN; ++n) acc[m][n] = 0.0f;

    // Precompute load indices
    // x tile: 128 rows x 16 k = 512 float4; 2 per thread.
    const int xr0 = (t) >> 2;          // row for f = t
    const int xc0 = (t) & 3;           // float4 index within the 16-k chunk
    const int xr1 = (t + 256) >> 2;
    const int xc1 = (t + 256) & 3;
    // W tile: 16 k x 64 n = 256 float4; 1 per thread.
    const int wk = t >> 4;             // 0..15
    const int wc = t & 15;             // 0..15

    const float* xg0 = x + (size_t)(block_row + xr0) * KDIM + xc0 * 4;
    const float* xg1 = x + (size_t)(block_row + xr1) * KDIM + xc1 * 4;
    const float* wg  = W + (size_t)wk * NDIM + wc * 4;

    for (int k0 = 0; k0 < KDIM; k0 += BK) {
        // ---- load x tile (scatter to [k][row]) ----
        {
            float4 v0 = *(const float4*)(xg0 + k0);
            xs[xc0 * 4 + 0][xr0] = v0.x;
            xs[xc0 * 4 + 1][xr0] = v0.y;
            xs[xc0 * 4 + 2][xr0] = v0.z;
            xs[xc0 * 4 + 3][xr0] = v0.w;
            float4 v1 = *(const float4*)(xg1 + k0);
            xs[xc1 * 4 + 0][xr1] = v1.x;
            xs[xc1 * 4 + 1][xr1] = v1.y;
            xs[xc1 * 4 + 2][xr1] = v1.z;
            xs[xc1 * 4 + 3][xr1] = v1.w;
        }
        // ---- load W tile ----
        {
            float4 v = *(const float4*)(wg + (size_t)k0 * NDIM);
            *(float4*)(&ws[wk][wc * 4]) = v;
        }
        __syncthreads();

#pragma unroll
        for (int k = 0; k < BK; ++k) {
            float xf[TM];
#pragma unroll
            for (int m = 0; m < TM; ++m) xf[m] = xs[k][tr * TM + m];
            float wf[TN];
#pragma unroll
            for (int n = 0; n < TN; ++n) wf[n] = ws[k][tc * TN + n];
#pragma unroll
            for (int m = 0; m < TM; ++m)
#pragma unroll
                for (int n = 0; n < TN; ++n)
                    acc[m][n] = fmaf(xf[m], wf[n], acc[m][n]);
        }
        __syncthreads();
    }

    // ---- store 8x4 microtile as float4 per row ----
#pragma unroll
    for (int m = 0; m < TM; ++m) {
        float4 v;
        v.x = acc[m][0]; v.y = acc[m][1]; v.z = acc[m][2]; v.w = acc[m][3];
        *(float4*)(out + (size_t)(block_row + tr * TM + m) * NDIM + tc * TN) = v;
    }
}

extern "C" void kernel_launch(void* const* d_in, const int* in_sizes, int n_in,
                              void* d_out, int out_size) {
    const float* x = (const float*)d_in[0];   // [65536, 512]
    const float* W = (const float*)d_in[1];   // [512, 64]
    float* out = (float*)d_out;               // [65536, 64]

    dim3 grid(BATCH / BM);   // 512 blocks
    dim3 block(THREADS);
    NN_57844619543085_kernel<<<grid, block>>>(x, W, out);
}

// round 3
// speedup vs baseline: 2.3509x; 2.3509x over previous
#include <cuda_runtime.h>
#include <cuda_bf16.h>
#include <stdint.h>

// out[B,N] = x[B,K] @ W[K,N];  B=65536, K=512, N=64, fp32.
// bf16 split-precision tensor-core GEMM:
//   x = x_hi + x_lo, W = W_hi + W_lo (bf16 each)
//   out = x_hi*W_hi + x_hi*W_lo + x_lo*W_hi   (fp32 accumulate in HMMA)
// Residual ~2^-17 per term -> rel_err ~2e-5.

#define BATCH 65536
#define KDIM  512
#define NDIM  64
#define BM    128
#define BK    64
#define NCHUNK (KDIM / BK)   // 8
#define THREADS 256

// smem layout (bytes): 128 rows x 128B per region, XOR-swizzled
#define XHI_OFF 0
#define XLO_OFF 16384
#define WHI_OFF 32768        // 64 n-rows x 128B ; WLO at +8192
#define SMEM_BYTES 49152

// Pre-packed W: per chunk c (0..7): 16KB = [hi: 64 n-rows x 128B][lo: same],
// n-row-major [n][k] bf16, byte-in-row = (klocal*2) ^ ((n&7)<<4).
__device__ __align__(16) unsigned char g_wpack[NCHUNK * 16384];

__global__ void wprep_kernel(const float* __restrict__ W) {
    int tid = blockIdx.x * blockDim.x + threadIdx.x;   // 0..32767
    int k = tid >> 6;        // 0..511
    int n = tid & 63;        // 0..63
    float v = W[k * NDIM + n];
    __nv_bfloat16 h = __float2bfloat16_rn(v);
    __nv_bfloat16 l = __float2bfloat16_rn(v - __bfloat162float(h));
    int c  = k >> 6;
    int kl = k & 63;
    int off = c * 16384 + n * 128 + ((kl * 2) ^ ((n & 7) << 4));
    *(__nv_bfloat16*)(g_wpack + off)        = h;
    *(__nv_bfloat16*)(g_wpack + off + 8192) = l;
}

__device__ __forceinline__ uint32_t packbf2(__nv_bfloat16 a, __nv_bfloat16 b) {
    __nv_bfloat162 t;
    t.x = a; t.y = b;
    return *reinterpret_cast<uint32_t*>(&t);
}

__device__ __forceinline__ void mma_bf16(float* d, const uint32_t* a, const uint32_t* b) {
    asm volatile(
        "mma.sync.aligned.m16n8k16.row.col.f32.bf16.bf16.f32 "
        "{%0,%1,%2,%3}, {%4,%5,%6,%7}, {%8,%9}, {%0,%1,%2,%3};\n"
        : "+f"(d[0]), "+f"(d[1]), "+f"(d[2]), "+f"(d[3])
        : "r"(a[0]), "r"(a[1]), "r"(a[2]), "r"(a[3]), "r"(b[0]), "r"(b[1]));
}

__device__ __forceinline__ void ldsm_x4(uint32_t* r, uint32_t saddr) {
    asm volatile("ldmatrix.sync.aligned.m8n8.x4.shared.b16 {%0,%1,%2,%3}, [%4];"
        : "=r"(r[0]), "=r"(r[1]), "=r"(r[2]), "=r"(r[3]) : "r"(saddr));
}

__global__ __launch_bounds__(THREADS, 2)
void NN_57844619543085_kernel(const float* __restrict__ x,
                              float* __restrict__ out) {
    __shared__ __align__(16) unsigned char sm[SMEM_BYTES];
    const uint32_t smbase = (uint32_t)__cvta_generic_to_shared(sm);

    const int t    = threadIdx.x;
    const int lane = t & 31;
    const int warp = t >> 5;
    const int wm   = warp >> 1;   // 0..3 : 32-row slab
    const int wn   = warp & 1;    // 0..1 : 32-col slab
    const int block_row = blockIdx.x * BM;

    float acc[2][4][4];
#pragma unroll
    for (int mt = 0; mt < 2; ++mt)
#pragma unroll
        for (int nt = 0; nt < 4; ++nt)
#pragma unroll
            for (int r = 0; r < 4; ++r) acc[mt][nt][r] = 0.0f;

    // ldmatrix lane decomposition
    const int sub  = lane >> 3;   // 0..3 : which 8x8 matrix
    const int lrow = lane & 7;    // row within matrix
    const int swz  = lrow << 4;   // XOR swizzle term (bits 4-6)

    const float* xg = x + (size_t)block_row * KDIM;

    for (int c = 0; c < NCHUNK; ++c) {
        if (c) __syncthreads();

        // ---- x chunk: load fp32, split to bf16 hi/lo, store swizzled ----
        // 128 rows x 32 pairs; warp covers one row (coalesced 256B), STS conflict-free.
#pragma unroll
        for (int i = 0; i < 16; ++i) {
            int idx = i * 256 + t;           // 0..4095
            int row = idx >> 5;              // 0..127
            int p   = idx & 31;              // k-pair
            float2 v = *(const float2*)(xg + (size_t)row * KDIM + c * BK + p * 2);
            __nv_bfloat16 h0 = __float2bfloat16_rn(v.x);
            __nv_bfloat16 h1 = __float2bfloat16_rn(v.y);
            __nv_bfloat16 l0 = __float2bfloat16_rn(v.x - __bfloat162float(h0));
            __nv_bfloat16 l1 = __float2bfloat16_rn(v.y - __bfloat162float(h1));
            int boff = row * 128 + ((p * 4) ^ ((row & 7) << 4));
            *(uint32_t*)(sm + XHI_OFF + boff) = packbf2(h0, h1);
            *(uint32_t*)(sm + XLO_OFF + boff) = packbf2(l0, l1);
        }
        // ---- W chunk: raw copy of pre-packed image (hi 8KB + lo 8KB) ----
#pragma unroll
        for (int i = 0; i < 4; ++i) {
            int g = i * 256 + t;             // 0..1023
            float4 v = *(const float4*)(g_wpack + c * 16384 + (size_t)g * 16);
            *(float4*)(sm + WHI_OFF + g * 16) = v;
        }
        __syncthreads();

        // ---- 4 k16 steps of MMAs ----
#pragma unroll
        for (int ks = 0; ks < 4; ++ks) {
            uint32_t ahi[2][4], alo[2][4], bhi[4][2], blo[4][2];
#pragma unroll
            for (int mt = 0; mt < 2; ++mt) {
                int ra = wm * 32 + mt * 16 + (sub & 1) * 8 + lrow;
                uint32_t aoff = ra * 128 + ((ks * 32 + (sub >> 1) * 16) ^ swz);
                ldsm_x4(ahi[mt], smbase + XHI_OFF + aoff);
                ldsm_x4(alo[mt], smbase + XLO_OFF + aoff);
            }
#pragma unroll
            for (int q = 0; q < 2; ++q) {
                int n = wn * 32 + (2 * q + (sub >> 1)) * 8 + lrow;
                uint32_t boff = n * 128 + ((ks * 32 + (sub & 1) * 16) ^ swz);
                uint32_t tmp[4];
                ldsm_x4(tmp, smbase + WHI_OFF + boff);
                bhi[2*q][0] = tmp[0]; bhi[2*q][1] = tmp[1];
                bhi[2*q+1][0] = tmp[2]; bhi[2*q+1][1] = tmp[3];
                ldsm_x4(tmp, smbase + WHI_OFF + 8192 + boff);
                blo[2*q][0] = tmp[0]; blo[2*q][1] = tmp[1];
                blo[2*q+1][0] = tmp[2]; blo[2*q+1][1] = tmp[3];
            }
#pragma unroll
            for (int mt = 0; mt < 2; ++mt)
#pragma unroll
                for (int nt = 0; nt < 4; ++nt) {
                    mma_bf16(acc[mt][nt], ahi[mt], bhi[nt]);
                    mma_bf16(acc[mt][nt], ahi[mt], blo[nt]);
                    mma_bf16(acc[mt][nt], alo[mt], bhi[nt]);
                }
        }
    }

    // ---- epilogue: fp32 stores, sector-aligned ----
#pragma unroll
    for (int mt = 0; mt < 2; ++mt)
#pragma unroll
        for (int nt = 0; nt < 4; ++nt) {
            int grow = block_row + wm * 32 + mt * 16 + (lane >> 2);
            int gcol = wn * 32 + nt * 8 + (lane & 3) * 2;
            float2 v01 = make_float2(acc[mt][nt][0], acc[mt][nt][1]);
            float2 v23 = make_float2(acc[mt][nt][2], acc[mt][nt][3]);
            *(float2*)(out + (size_t)grow * NDIM + gcol)       = v01;
            *(float2*)(out + (size_t)(grow + 8) * NDIM + gcol) = v23;
        }
}

extern "C" void kernel_launch(void* const* d_in, const int* in_sizes, int n_in,
                              void* d_out, int out_size) {
    const float* x = (const float*)d_in[0];   // [65536, 512]
    const float* W = (const float*)d_in[1];   // [512, 64]
    float* out = (float*)d_out;               // [65536, 64]

    wprep_kernel<<<128, 256>>>(W);
    NN_57844619543085_kernel<<<BATCH / BM, THREADS>>>(x, out);
}